// round 10
// baseline (speedup 1.0000x reference)
#include <cuda_runtime.h>
#include <cuda_bf16.h>
#include <cuda_fp16.h>
#include <cstdint>

// Problem constants
#define BB   8
#define CIN  64
#define HH   64
#define WW   64
#define OCH_OFF 1152
#define OCH_TOT 1728
#define OCP     1792          // padded oc (14 * 128)
#define OC_FIN  128
#define MAXOFF  16.0f
#define PADW 100              // padded plane 100x100, border 17
#define QMAX 16256.0f         // 15-bit quant range (127*128)

// Scratch
__device__ float g_om[(size_t)BB * OCH_TOT * HH * WW];   // conv out [b][r][y][x]
__device__ float g_wt[576 * 128];                        // w_conv transposed [ck][oc]
__device__ float g_xpad[(size_t)BB * CIN * PADW * PADW]; // zero-padded x
// int8 quantized shifted x: [kj][b][yy 0..65][cc 0..1][px 0..63][cic 0..31]
__device__ char g_xq1[3 * 8 * 66 * 2 * 64 * 32];
__device__ char g_xq0[3 * 8 * 66 * 2 * 64 * 32];
// int8 quantized conv weights: [t][cc 0..1][ocp][cic 0..31]
__device__ char g_wq1[9 * 2 * OCP * 32];
__device__ char g_wq0[9 * 2 * OCP * 32];
__device__ float g_sw[OCP];          // per-oc weight scale
__device__ unsigned g_xmax_bits;     // |x| max (bits)
__device__ float g_sx, g_sxr;        // x scale, reciprocal

// ======================= helpers =======================
__device__ __forceinline__ uint32_t smem_u32(const void* p) {
    uint32_t a;
    asm("{ .reg .u64 t; cvta.to.shared.u64 t, %1; cvt.u32.u64 %0, t; }"
        : "=r"(a) : "l"(p));
    return a;
}
__device__ __forceinline__ void ldm_x4(uint32_t* r, uint32_t addr) {
    asm volatile("ldmatrix.sync.aligned.m8n8.x4.shared.b16 {%0,%1,%2,%3}, [%4];"
                 : "=r"(r[0]), "=r"(r[1]), "=r"(r[2]), "=r"(r[3]) : "r"(addr));
}
__device__ __forceinline__ void mma_s8(int* d, const uint32_t* a,
                                       uint32_t b0, uint32_t b1) {
    asm volatile(
        "mma.sync.aligned.m16n8k32.row.col.s32.s8.s8.s32 "
        "{%0,%1,%2,%3}, {%4,%5,%6,%7}, {%8,%9}, {%0,%1,%2,%3};"
        : "+r"(d[0]), "+r"(d[1]), "+r"(d[2]), "+r"(d[3])
        : "r"(a[0]), "r"(a[1]), "r"(a[2]), "r"(a[3]), "r"(b0), "r"(b1));
}

// ---------------- packed f32x2 helpers (deform kernel) ----------------
__device__ __forceinline__ unsigned long long ffma2(unsigned long long a,
                                                    unsigned long long b,
                                                    unsigned long long c) {
    unsigned long long d;
    asm("fma.rn.f32x2 %0, %1, %2, %3;" : "=l"(d) : "l"(a), "l"(b), "l"(c));
    return d;
}
__device__ __forceinline__ unsigned long long pack2(float lo, float hi) {
    unsigned long long d;
    asm("mov.b64 %0, {%1, %2};" : "=l"(d) : "f"(lo), "f"(hi));
    return d;
}
__device__ __forceinline__ void unpack2(unsigned long long v, float& lo, float& hi) {
    asm("mov.b64 {%0, %1}, %2;" : "=f"(lo), "=f"(hi) : "l"(v));
}

// ======================= Prep kernels =======================
__global__ void prep_xmax(const float* __restrict__ x, int n) {
    __shared__ unsigned sm[256];
    unsigned m = 0;
    for (int i = blockIdx.x * 256 + threadIdx.x; i < n; i += gridDim.x * 256)
        m = max(m, __float_as_uint(fabsf(x[i])));
    sm[threadIdx.x] = m;
    __syncthreads();
    for (int s = 128; s > 0; s >>= 1) {
        if (threadIdx.x < s) sm[threadIdx.x] = max(sm[threadIdx.x], sm[threadIdx.x + s]);
        __syncthreads();
    }
    if (threadIdx.x == 0) atomicMax(&g_xmax_bits, sm[0]);
}

__global__ void prep_sx() {
    float mx = __uint_as_float(g_xmax_bits);
    if (!(mx > 0.f)) mx = 1.f;
    g_sx = mx / QMAX;
    g_sxr = QMAX / mx;
}

__global__ void prep_xq(const float* __restrict__ x) {
    int i = blockIdx.x * 256 + threadIdx.x;
    const int TOT = 3 * 8 * 66 * 2 * 64 * 32;
    if (i >= TOT) return;
    int cic = i & 31;
    int t1 = i >> 5;
    int px = t1 & 63;
    int t2 = t1 >> 6;
    int cc = t2 & 1;
    int t3 = t2 >> 1;
    int yy = t3 % 66;
    int t4 = t3 / 66;
    int b  = t4 & 7;
    int kj = t4 >> 3;
    int c = cc * 32 + cic;
    int sy = yy - 1, sx = px + kj - 1;
    float v = 0.f;
    if (sy >= 0 && sy < HH && sx >= 0 && sx < WW)
        v = x[(((size_t)b * CIN + c) * HH + sy) * WW + sx];
    int X = __float2int_rn(v * g_sxr);
    int x1 = (X + 64) >> 7;
    int x0 = X - (x1 << 7);
    g_xq1[i] = (char)x1;
    g_xq0[i] = (char)x0;
}

// per-oc scale + quantize weights. 1 thread per padded oc.
__global__ void prep_wq(const float* __restrict__ w_off, const float* __restrict__ w_mod) {
    int oc = blockIdx.x * 256 + threadIdx.x;
    if (oc >= OCP) return;
    const float* src = nullptr;
    int r = 0;
    if (oc < OCH_OFF)      { src = w_off; r = oc; }
    else if (oc < OCH_TOT) { src = w_mod; r = oc - OCH_OFF; }
    float mx = 0.f;
    if (src)
        for (int j = 0; j < 576; j++)
            mx = fmaxf(mx, fabsf(src[(size_t)r * 576 + j]));
    if (!(mx > 0.f)) mx = 1.f;
    float s = mx / QMAX, sr = QMAX / mx;
    g_sw[oc] = s;
    for (int c = 0; c < 64; c++) {
        for (int t = 0; t < 9; t++) {
            float v = src ? src[((size_t)r * 64 + c) * 9 + t] : 0.f;
            int W = __float2int_rn(v * sr);
            int w1 = (W + 64) >> 7;
            int w0 = W - (w1 << 7);
            int cc = c >> 5, cic = c & 31;
            size_t idx = ((size_t)(t * 2 + cc) * OCP + oc) * 32 + cic;
            g_wq1[idx] = (char)w1;
            g_wq0[idx] = (char)w0;
        }
    }
}

__global__ void prep_xpad(const float* __restrict__ x) {
    int i = blockIdx.x * 256 + threadIdx.x;
    const int TOT = BB * CIN * PADW * PADW;
    if (i >= TOT) return;
    int xx = i % PADW;
    int t1 = i / PADW;
    int yy = t1 % PADW;
    int bc = t1 / PADW;
    int sy = yy - 17, sx = xx - 17;
    float v = 0.f;
    if (sy >= 0 && sy < HH && sx >= 0 && sx < WW)
        v = x[((size_t)bc * HH + sy) * WW + sx];
    g_xpad[i] = v;
}

__global__ void transpose_wconv(const float* __restrict__ w_conv) {
    int i = blockIdx.x * 256 + threadIdx.x;
    if (i < OC_FIN * 576) {
        int oc = i / 576, ck = i % 576;
        g_wt[ck * 128 + oc] = w_conv[i];
    }
}

// ======================= Conv kernel: int8 3-IMMA split ===================
// CTA: 128 oc x 64 px (1 image row of one b). 8 warps: wm = w&3 (32 oc),
// wn = (w>>2)&1 (32 px). K = 9 taps x 2 chunks of 32 channels = 18 steps.
// SMEM per buffer: A1[128][48] @0, A0 @6144, B1[64][48] @12288, B0 @15360.
#define SROW 48
#define BUFSZ 18432
__global__ __launch_bounds__(256) void conv_imma_kernel(
    const float* __restrict__ b_off, const float* __restrict__ b_mod)
{
    __shared__ __align__(16) char smem[2 * BUFSZ];   // 36 KB
    const uint32_t sb = smem_u32(smem);
    const int tid = threadIdx.x;
    const int lane = tid & 31;
    const int w = tid >> 5;
    const int wm = w & 3;
    const int wn = (w >> 2) & 1;
    const int ocBase = blockIdx.x * 128;
    const int y = blockIdx.y;
    const int b = blockIdx.z;

    int d1[2][4][4], d2[2][4][4];
#pragma unroll
    for (int mt = 0; mt < 2; mt++)
#pragma unroll
        for (int nt = 0; nt < 4; nt++)
#pragma unroll
            for (int e = 0; e < 4; e++) { d1[mt][nt][e] = 0; d2[mt][nt][e] = 0; }

    auto stage = [&](int s, int buf) {
        const int t = s >> 1, cc = s & 1;
        const int ki = t / 3, kj = t - ki * 3;
        char* base = smem + buf * BUFSZ;
        const int yy = y + ki;
#pragma unroll
        for (int ii = 0; ii < 3; ii++) {
            int i = tid + ii * 256;
            if (i < 512) {
                int hh = i >> 8, oc = (i >> 1) & 127, j = i & 1;
                const char* src = (hh ? g_wq0 : g_wq1)
                    + (((size_t)(t * 2 + cc) * OCP + ocBase + oc) << 5) + j * 16;
                *(uint4*)(base + hh * 6144 + oc * SROW + j * 16) = *(const uint4*)src;
            } else {
                int i2 = i - 512;
                int hh = i2 >> 7, px = (i2 >> 1) & 63, j = i2 & 1;
                const char* src = (hh ? g_xq0 : g_xq1)
                    + (((size_t)(((kj * 8 + b) * 66 + yy) * 2 + cc) * 64 + px) << 5)
                    + j * 16;
                *(uint4*)(base + 12288 + hh * 3072 + px * SROW + j * 16) = *(const uint4*)src;
            }
        }
    };

    stage(0, 0);
    __syncthreads();

    const int arowL = (lane & 7) + ((lane >> 3) & 1) * 8;
    const int acolB = ((lane >> 4) & 1) * 16;

    for (int s = 0; s < 18; s++) {
        const int buf = s & 1;
        if (s + 1 < 18) stage(s + 1, 1 - buf);

        const uint32_t sA = sb + buf * BUFSZ;
        const uint32_t sB = sA + 12288;

        uint32_t aw1[2][4], aw0[2][4];
#pragma unroll
        for (int mt = 0; mt < 2; mt++) {
            uint32_t arow = (wm * 32 + mt * 16 + arowL) * SROW + acolB;
            ldm_x4(aw1[mt], sA + arow);
            ldm_x4(aw0[mt], sA + 6144 + arow);
        }

#pragma unroll
        for (int pg = 0; pg < 2; pg++) {
            uint32_t bx1[4], bx0[4];
            uint32_t brow = (wn * 32 + pg * 16 + arowL) * SROW + acolB;
            ldm_x4(bx1, sB + brow);
            ldm_x4(bx0, sB + 3072 + brow);
#pragma unroll
            for (int mt = 0; mt < 2; mt++) {
#pragma unroll
                for (int q = 0; q < 2; q++) {
                    mma_s8(d1[mt][pg * 2 + q], aw1[mt], bx1[q], bx1[q + 2]);
                    mma_s8(d2[mt][pg * 2 + q], aw1[mt], bx0[q], bx0[q + 2]);
                    mma_s8(d2[mt][pg * 2 + q], aw0[mt], bx1[q], bx1[q + 2]);
                }
            }
        }
        __syncthreads();
    }

    const int ocW = ocBase + wm * 32;
    if (ocW >= OCH_TOT) return;
    const float sx = g_sx;
#pragma unroll
    for (int mt = 0; mt < 2; mt++) {
        int r0 = ocW + mt * 16 + (lane >> 2);
        int r1 = r0 + 8;
        float sc0 = sx * g_sw[r0], sc1 = sx * g_sw[r1];
        float bias0 = (r0 < OCH_OFF) ? __ldg(&b_off[r0]) : __ldg(&b_mod[r0 - OCH_OFF]);
        float bias1 = (r1 < OCH_OFF) ? __ldg(&b_off[r1]) : __ldg(&b_mod[r1 - OCH_OFF]);
        bool c0 = r0 < OCH_OFF, c1 = r1 < OCH_OFF;
        float* base0 = &g_om[(((size_t)b * OCH_TOT + r0) * HH + y) * WW];
        float* base1 = &g_om[(((size_t)b * OCH_TOT + r1) * HH + y) * WW];
#pragma unroll
        for (int nt = 0; nt < 4; nt++) {
            int col = wn * 32 + nt * 8 + (lane & 3) * 2;
            float2 v0, v1;
            v0.x = sc0 * (16384.f * (float)d1[mt][nt][0] + 128.f * (float)d2[mt][nt][0]) + bias0;
            v0.y = sc0 * (16384.f * (float)d1[mt][nt][1] + 128.f * (float)d2[mt][nt][1]) + bias0;
            v1.x = sc1 * (16384.f * (float)d1[mt][nt][2] + 128.f * (float)d2[mt][nt][2]) + bias1;
            v1.y = sc1 * (16384.f * (float)d1[mt][nt][3] + 128.f * (float)d2[mt][nt][3]) + bias1;
            if (c0) {
                v0.x = fminf(fmaxf(v0.x, -MAXOFF), MAXOFF);
                v0.y = fminf(fmaxf(v0.y, -MAXOFF), MAXOFF);
            }
            if (c1) {
                v1.x = fminf(fmaxf(v1.x, -MAXOFF), MAXOFF);
                v1.y = fminf(fmaxf(v1.y, -MAXOFF), MAXOFF);
            }
            *(float2*)(base0 + col) = v0;
            *(float2*)(base1 + col) = v1;
        }
    }
}

// ======================= Deform + final GEMM (FFMA2, padded sampling) =====
__global__ __launch_bounds__(256) void deform_gemm_kernel(float* __restrict__ out)
{
    const int y = blockIdx.x;
    const int b = blockIdx.y;
    const int tid = threadIdx.x;
    const int tx = tid & 15;
    const int ty = tid >> 4;
    const int px0 = tx * 4;
    const int oc0 = ty * 8;

    __shared__ __align__(16) float ss[4 * 9 * 64];
    __shared__ __align__(16) float wcs[36][128];

    unsigned long long acc2[4][4];
#pragma unroll
    for (int p = 0; p < 4; p++)
#pragma unroll
        for (int j = 0; j < 4; j++) acc2[p][j] = 0ull;

    const float* xpb = g_xpad + (size_t)b * CIN * (PADW * PADW);
    const float* omb = g_om + (size_t)b * OCH_TOT * (HH * WW);

    for (int c0 = 0; c0 < CIN; c0 += 4) {
        for (int idx = tid; idx < 36 * 128; idx += 256) {
            ((float*)wcs)[idx] = g_wt[(c0 * 9 + (idx >> 7)) * 128 + (idx & 127)];
        }
        for (int s = tid; s < 4 * 9 * 64; s += 256) {
            int px = s & 63;
            int k  = (s >> 6) % 9;
            int cc = s / 576;
            int c  = c0 + cc;
            int ki = k / 3, kj = k % 3;
            float dy = __ldg(omb + (size_t)(c * 18 + 2 * k) * 4096 + y * WW + px);
            float dx = __ldg(omb + (size_t)(c * 18 + 2 * k + 1) * 4096 + y * WW + px);
            float m  = __ldg(omb + (size_t)(OCH_OFF + c * 9 + k) * 4096 + y * WW + px);
            float py  = dy + (float)(y + ki + 16);
            float pxf = dx + (float)(px + kj + 16);
            int iy = (int)py, ix = (int)pxf;
            float wy = py - (float)iy, wx = pxf - (float)ix;
            const float* p = xpb + (size_t)c * (PADW * PADW) + iy * PADW + ix;
            float v00 = __ldg(p), v01 = __ldg(p + 1);
            float v10 = __ldg(p + PADW), v11 = __ldg(p + PADW + 1);
            float t0 = v00 + wx * (v01 - v00);
            float t1 = v10 + wx * (v11 - v10);
            ss[s] = (t0 + wy * (t1 - t0)) * m;
        }
        __syncthreads();

#pragma unroll
        for (int ck = 0; ck < 36; ck++) {
            float4 sv4 = *(const float4*)&ss[ck * 64 + px0];
            unsigned long long sp[4];
            sp[0] = pack2(sv4.x, sv4.x);
            sp[1] = pack2(sv4.y, sv4.y);
            sp[2] = pack2(sv4.z, sv4.z);
            sp[3] = pack2(sv4.w, sv4.w);
            ulonglong2 w0 = *(const ulonglong2*)&wcs[ck][oc0];
            ulonglong2 w1 = *(const ulonglong2*)&wcs[ck][oc0 + 4];
#pragma unroll
            for (int j = 0; j < 4; j++) {
                acc2[0][j] = ffma2(w0.x, sp[j], acc2[0][j]);
                acc2[1][j] = ffma2(w0.y, sp[j], acc2[1][j]);
                acc2[2][j] = ffma2(w1.x, sp[j], acc2[2][j]);
                acc2[3][j] = ffma2(w1.y, sp[j], acc2[3][j]);
            }
        }
        __syncthreads();
    }

#pragma unroll
    for (int p = 0; p < 4; p++) {
        float lo[4], hi[4];
#pragma unroll
        for (int j = 0; j < 4; j++) unpack2(acc2[p][j], lo[j], hi[j]);
        float4 vlo = make_float4(lo[0], lo[1], lo[2], lo[3]);
        float4 vhi = make_float4(hi[0], hi[1], hi[2], hi[3]);
        int oc = oc0 + 2 * p;
        *(float4*)&out[(((size_t)b * OC_FIN + oc) * HH + y) * WW + px0] = vlo;
        *(float4*)&out[(((size_t)b * OC_FIN + oc + 1) * HH + y) * WW + px0] = vhi;
    }
}

// ---------------------------------------------------------------------------
extern "C" void kernel_launch(void* const* d_in, const int* in_sizes, int n_in,
                              void* d_out, int out_size)
{
    const float* x      = (const float*)d_in[0];
    const float* w_off  = (const float*)d_in[1];
    const float* b_off  = (const float*)d_in[2];
    const float* w_mod  = (const float*)d_in[3];
    const float* b_mod  = (const float*)d_in[4];
    const float* w_conv = (const float*)d_in[5];
    float* out = (float*)d_out;

    const int NX = BB * CIN * HH * WW;
    prep_xmax<<<512, 256>>>(x, NX);
    prep_sx<<<1, 1>>>();
    prep_xq<<<(3 * 8 * 66 * 2 * 64 * 32 + 255) / 256, 256>>>(x);
    prep_wq<<<(OCP + 255) / 256, 256>>>(w_off, w_mod);
    prep_xpad<<<(BB * CIN * PADW * PADW + 255) / 256, 256>>>(x);
    transpose_wconv<<<(OC_FIN * 576 + 255) / 256, 256>>>(w_conv);
    conv_imma_kernel<<<dim3(14, 64, 8), 256>>>(b_off, b_mod);
    deform_gemm_kernel<<<dim3(HH, BB), 256>>>(out);
}

// round 11
// speedup vs baseline: 2.3277x; 2.3277x over previous
#include <cuda_runtime.h>
#include <cuda_bf16.h>
#include <cuda_fp16.h>
#include <cstdint>

// Problem constants
#define BB   8
#define CIN  64
#define HH   64
#define WW   64
#define OCH_OFF 1152
#define OCH_TOT 1728
#define OCP     1792          // padded oc (14 * 128)
#define OC_FIN  128
#define MAXOFF  16.0f
#define PADW 100              // padded plane 100x100, border 17

// Scratch
__device__ float g_om[(size_t)BB * OCH_TOT * HH * WW];   // conv out [b][r][y][x]
__device__ float g_wt[576 * 128];                        // w_conv transposed [ck][oc]
// zero-padded x: [b][c][100][100], (yy,xx) = (y+17, x+17)
__device__ float g_xpad[(size_t)BB * CIN * PADW * PADW];
// shifted x, fp16: g_xth[kj][b][yy 0..65][cc 0..3][px 0..63][cic 0..15]
__device__ __half g_xth[3 * 8 * 66 * 4 * 64 * 16];
// conv weights fp16 split: g_wh[t][cc][ocp][cic] (zeros oc>=1728)
__device__ __half g_wh_hi[9 * 4 * OCP * 16];
__device__ __half g_wh_lo[9 * 4 * OCP * 16];

// ======================= helpers =======================
__device__ __forceinline__ uint32_t smem_u32(const void* p) {
    uint32_t a;
    asm("{ .reg .u64 t; cvta.to.shared.u64 t, %1; cvt.u32.u64 %0, t; }"
        : "=r"(a) : "l"(p));
    return a;
}
__device__ __forceinline__ void ldm_x4(uint32_t* r, uint32_t addr) {
    asm volatile("ldmatrix.sync.aligned.m8n8.x4.shared.b16 {%0,%1,%2,%3}, [%4];"
                 : "=r"(r[0]), "=r"(r[1]), "=r"(r[2]), "=r"(r[3]) : "r"(addr));
}
__device__ __forceinline__ void mma_f16(float* d, const uint32_t* a,
                                        uint32_t b0, uint32_t b1) {
    asm volatile(
        "mma.sync.aligned.m16n8k16.row.col.f32.f16.f16.f32 "
        "{%0,%1,%2,%3}, {%4,%5,%6,%7}, {%8,%9}, {%0,%1,%2,%3};"
        : "+f"(d[0]), "+f"(d[1]), "+f"(d[2]), "+f"(d[3])
        : "r"(a[0]), "r"(a[1]), "r"(a[2]), "r"(a[3]), "r"(b0), "r"(b1));
}

// ---------------- packed f32x2 helpers (deform kernel) ----------------
__device__ __forceinline__ unsigned long long ffma2(unsigned long long a,
                                                    unsigned long long b,
                                                    unsigned long long c) {
    unsigned long long d;
    asm("fma.rn.f32x2 %0, %1, %2, %3;" : "=l"(d) : "l"(a), "l"(b), "l"(c));
    return d;
}
__device__ __forceinline__ unsigned long long pack2(float lo, float hi) {
    unsigned long long d;
    asm("mov.b64 %0, {%1, %2};" : "=l"(d) : "f"(lo), "f"(hi));
    return d;
}
__device__ __forceinline__ void unpack2(unsigned long long v, float& lo, float& hi) {
    asm("mov.b64 {%0, %1}, %2;" : "=f"(lo), "=f"(hi) : "l"(v));
}

// ======================= Prep kernels =======================
__global__ void prep_xth(const float* __restrict__ x) {
    int i = blockIdx.x * 256 + threadIdx.x;
    const int TOT = 3 * 8 * 66 * 4 * 64 * 16;
    if (i >= TOT) return;
    int cic = i & 15;
    int t1 = i >> 4;
    int px = t1 & 63;
    int t2 = t1 >> 6;
    int cc = t2 & 3;
    int t3 = t2 >> 2;
    int yy = t3 % 66;
    int t4 = t3 / 66;
    int b  = t4 & 7;
    int kj = t4 >> 3;
    int c = cc * 16 + cic;
    int sy = yy - 1, sx = px + kj - 1;
    float v = 0.f;
    if (sy >= 0 && sy < HH && sx >= 0 && sx < WW)
        v = x[(((size_t)b * CIN + c) * HH + sy) * WW + sx];
    g_xth[i] = __float2half(v);
}

__global__ void prep_wh(const float* __restrict__ w_off, const float* __restrict__ w_mod) {
    int i = blockIdx.x * 256 + threadIdx.x;
    const int TOT = 9 * 4 * OCP * 16;
    if (i >= TOT) return;
    int cic = i & 15;
    int t1 = i >> 4;
    int oc = t1 % OCP;
    int tcc = t1 / OCP;
    int cc = tcc & 3;
    int tp = tcc >> 2;
    int c = cc * 16 + cic;
    float v = 0.f;
    if (oc < OCH_OFF)      v = w_off[((size_t)oc * CIN + c) * 9 + tp];
    else if (oc < OCH_TOT) v = w_mod[((size_t)(oc - OCH_OFF) * CIN + c) * 9 + tp];
    __half h = __float2half(v);
    g_wh_hi[i] = h;
    g_wh_lo[i] = __float2half(v - __half2float(h));
}

__global__ void prep_xpad(const float* __restrict__ x) {
    int i = blockIdx.x * 256 + threadIdx.x;
    const int TOT = BB * CIN * PADW * PADW;
    if (i >= TOT) return;
    int xx = i % PADW;
    int t1 = i / PADW;
    int yy = t1 % PADW;
    int bc = t1 / PADW;
    int sy = yy - 17, sx = xx - 17;
    float v = 0.f;
    if (sy >= 0 && sy < HH && sx >= 0 && sx < WW)
        v = x[((size_t)bc * HH + sy) * WW + sx];
    g_xpad[i] = v;
}

__global__ void transpose_wconv(const float* __restrict__ w_conv) {
    int i = blockIdx.x * 256 + threadIdx.x;
    if (i < OC_FIN * 576) {
        int oc = i / 576, ck = i % 576;
        g_wt[ck * 128 + oc] = w_conv[i];
    }
}

// ======================= Conv kernel: fp16 2-MMA split, 4-row CTA =========
// CTA: 128 oc x 256 px (4 image rows of one b). 16 warps: wm = w&3 (32 oc),
// wn = w>>2 (row 0..3). Warp tile 32 oc x 64 px. K = 9 taps x 4 chunks of 16.
// SMEM double buffer of {A_hi[128][48] ; A_lo[128][48] ; B[256][48]} = 48 KB.
#define SROW 48
#define ASZ 6144               // 128*48
#define BUFSZ 24576            // A_hi + A_lo + B(256 rows)
__global__ __launch_bounds__(512) void conv_mma_kernel(
    const float* __restrict__ b_off, const float* __restrict__ b_mod)
{
    __shared__ __align__(16) char smem[2 * BUFSZ];   // 48 KB
    const uint32_t sb = smem_u32(smem);
    const int tid = threadIdx.x;
    const int lane = tid & 31;
    const int w = tid >> 5;
    const int wm = w & 3;
    const int wn = w >> 2;          // 0..3
    const int ocBase = blockIdx.x * 128;
    const int y0 = blockIdx.y * 4;
    const int b  = blockIdx.z;

    float d[2][8][4];
#pragma unroll
    for (int mt = 0; mt < 2; mt++)
#pragma unroll
        for (int nt = 0; nt < 8; nt++)
#pragma unroll
            for (int e = 0; e < 4; e++) d[mt][nt][e] = 0.f;

    auto stage = [&](int s, int buf) {
        const int t = s >> 2, cc = s & 3;
        const int ki = t / 3, kj = t - ki * 3;
        char* base = smem + buf * BUFSZ;
#pragma unroll
        for (int ii = 0; ii < 2; ii++) {
            int i = tid + ii * 512;
            if (i < 512) {
                int hh = i >> 8, oc = (i >> 1) & 127, j = i & 1;
                const __half* src = (hh ? g_wh_lo : g_wh_hi)
                    + (((size_t)(t * 4 + cc) * OCP + ocBase + oc) << 4) + j * 8;
                *(uint4*)(base + hh * ASZ + oc * SROW + j * 16) = *(const uint4*)src;
            } else {
                int i2 = i - 512;
                int px = i2 >> 1, j = i2 & 1;
                int yy = y0 + (px >> 6) + ki;
                const __half* src = g_xth
                    + ((size_t)(((kj * 8 + b) * 66 + yy) * 4 + cc) << 10)
                    + ((px & 63) << 4) + j * 8;
                *(uint4*)(base + 2 * ASZ + px * SROW + j * 16) = *(const uint4*)src;
            }
        }
    };

    stage(0, 0);
    __syncthreads();

    const int arowL = (lane & 7) + ((lane >> 3) & 1) * 8;
    const int acolB = ((lane >> 4) & 1) * 16;

    for (int s = 0; s < 36; s++) {
        const int buf = s & 1;
        if (s + 1 < 36) stage(s + 1, 1 - buf);

        const uint32_t sA = sb + buf * BUFSZ;
        const uint32_t sB = sA + 2 * ASZ;

        uint32_t a[2][2][4];
#pragma unroll
        for (int mt = 0; mt < 2; mt++)
#pragma unroll
            for (int hh = 0; hh < 2; hh++)
                ldm_x4(a[mt][hh],
                       sA + hh * ASZ + (wm * 32 + mt * 16 + arowL) * SROW + acolB);

#pragma unroll
        for (int p = 0; p < 4; p++) {
            uint32_t bh[4];
            ldm_x4(bh, sB + (wn * 64 + p * 16 + arowL) * SROW + acolB);
#pragma unroll
            for (int mt = 0; mt < 2; mt++) {
#pragma unroll
                for (int q = 0; q < 2; q++) {
                    float* dd = d[mt][p * 2 + q];
                    mma_f16(dd, a[mt][0], bh[q], bh[q + 2]);   // Wh * X
                    mma_f16(dd, a[mt][1], bh[q], bh[q + 2]);   // Wl * X
                }
            }
        }
        __syncthreads();
    }

    const int ocW = ocBase + wm * 32;
    if (ocW >= OCH_TOT) return;
    const int y = y0 + wn;
#pragma unroll
    for (int mt = 0; mt < 2; mt++) {
        int r0 = ocW + mt * 16 + (lane >> 2);
        int r1 = r0 + 8;
        float bias0 = (r0 < OCH_OFF) ? __ldg(&b_off[r0]) : __ldg(&b_mod[r0 - OCH_OFF]);
        float bias1 = (r1 < OCH_OFF) ? __ldg(&b_off[r1]) : __ldg(&b_mod[r1 - OCH_OFF]);
        bool c0 = r0 < OCH_OFF, c1 = r1 < OCH_OFF;
        float* base0 = &g_om[(((size_t)b * OCH_TOT + r0) * HH + y) * WW];
        float* base1 = &g_om[(((size_t)b * OCH_TOT + r1) * HH + y) * WW];
#pragma unroll
        for (int nt = 0; nt < 8; nt++) {
            int col = nt * 8 + (lane & 3) * 2;
            float2 v0, v1;
            v0.x = d[mt][nt][0] + bias0; v0.y = d[mt][nt][1] + bias0;
            v1.x = d[mt][nt][2] + bias1; v1.y = d[mt][nt][3] + bias1;
            if (c0) {
                v0.x = fminf(fmaxf(v0.x, -MAXOFF), MAXOFF);
                v0.y = fminf(fmaxf(v0.y, -MAXOFF), MAXOFF);
            }
            if (c1) {
                v1.x = fminf(fmaxf(v1.x, -MAXOFF), MAXOFF);
                v1.y = fminf(fmaxf(v1.y, -MAXOFF), MAXOFF);
            }
            *(float2*)(base0 + col) = v0;
            *(float2*)(base1 + col) = v1;
        }
    }
}

// ======================= Deform + final GEMM (FFMA2, padded sampling) =====
// CTA = one (b, y) row: 64 px x 128 oc. 256 threads; channel chunks of 4.
__global__ __launch_bounds__(256) void deform_gemm_kernel(float* __restrict__ out)
{
    const int y = blockIdx.x;
    const int b = blockIdx.y;
    const int tid = threadIdx.x;
    const int tx = tid & 15;
    const int ty = tid >> 4;
    const int px0 = tx * 4;
    const int oc0 = ty * 8;

    __shared__ __align__(16) float ss[4 * 9 * 64];
    __shared__ __align__(16) float wcs[36][128];

    unsigned long long acc2[4][4];
#pragma unroll
    for (int p = 0; p < 4; p++)
#pragma unroll
        for (int j = 0; j < 4; j++) acc2[p][j] = 0ull;

    const float* xpb = g_xpad + (size_t)b * CIN * (PADW * PADW);
    const float* omb = g_om + (size_t)b * OCH_TOT * (HH * WW);

    for (int c0 = 0; c0 < CIN; c0 += 4) {
        for (int idx = tid; idx < 36 * 128; idx += 256) {
            ((float*)wcs)[idx] = g_wt[(c0 * 9 + (idx >> 7)) * 128 + (idx & 127)];
        }
        for (int s = tid; s < 4 * 9 * 64; s += 256) {
            int px = s & 63;
            int k  = (s >> 6) % 9;
            int cc = s / 576;
            int c  = c0 + cc;
            int ki = k / 3, kj = k % 3;
            float dy = __ldg(omb + (size_t)(c * 18 + 2 * k) * 4096 + y * WW + px);
            float dx = __ldg(omb + (size_t)(c * 18 + 2 * k + 1) * 4096 + y * WW + px);
            float m  = __ldg(omb + (size_t)(OCH_OFF + c * 9 + k) * 4096 + y * WW + px);
            // padded-plane coords (always in [0, 97])
            float py  = dy + (float)(y + ki + 16);
            float pxf = dx + (float)(px + kj + 16);
            int iy = (int)py, ix = (int)pxf;
            float wy = py - (float)iy, wx = pxf - (float)ix;
            const float* p = xpb + (size_t)c * (PADW * PADW) + iy * PADW + ix;
            float v00 = __ldg(p), v01 = __ldg(p + 1);
            float v10 = __ldg(p + PADW), v11 = __ldg(p + PADW + 1);
            float t0 = v00 + wx * (v01 - v00);
            float t1 = v10 + wx * (v11 - v10);
            ss[s] = (t0 + wy * (t1 - t0)) * m;
        }
        __syncthreads();

#pragma unroll
        for (int ck = 0; ck < 36; ck++) {
            float4 sv4 = *(const float4*)&ss[ck * 64 + px0];
            unsigned long long sp[4];
            sp[0] = pack2(sv4.x, sv4.x);
            sp[1] = pack2(sv4.y, sv4.y);
            sp[2] = pack2(sv4.z, sv4.z);
            sp[3] = pack2(sv4.w, sv4.w);
            ulonglong2 w0 = *(const ulonglong2*)&wcs[ck][oc0];
            ulonglong2 w1 = *(const ulonglong2*)&wcs[ck][oc0 + 4];
#pragma unroll
            for (int j = 0; j < 4; j++) {
                acc2[0][j] = ffma2(w0.x, sp[j], acc2[0][j]);
                acc2[1][j] = ffma2(w0.y, sp[j], acc2[1][j]);
                acc2[2][j] = ffma2(w1.x, sp[j], acc2[2][j]);
                acc2[3][j] = ffma2(w1.y, sp[j], acc2[3][j]);
            }
        }
        __syncthreads();
    }

#pragma unroll
    for (int p = 0; p < 4; p++) {
        float lo[4], hi[4];
#pragma unroll
        for (int j = 0; j < 4; j++) unpack2(acc2[p][j], lo[j], hi[j]);
        float4 vlo = make_float4(lo[0], lo[1], lo[2], lo[3]);
        float4 vhi = make_float4(hi[0], hi[1], hi[2], hi[3]);
        int oc = oc0 + 2 * p;
        *(float4*)&out[(((size_t)b * OC_FIN + oc) * HH + y) * WW + px0] = vlo;
        *(float4*)&out[(((size_t)b * OC_FIN + oc + 1) * HH + y) * WW + px0] = vhi;
    }
}

// ---------------------------------------------------------------------------
extern "C" void kernel_launch(void* const* d_in, const int* in_sizes, int n_in,
                              void* d_out, int out_size)
{
    const float* x      = (const float*)d_in[0];
    const float* w_off  = (const float*)d_in[1];
    const float* b_off  = (const float*)d_in[2];
    const float* w_mod  = (const float*)d_in[3];
    const float* b_mod  = (const float*)d_in[4];
    const float* w_conv = (const float*)d_in[5];
    float* out = (float*)d_out;

    prep_xth<<<(3 * 8 * 66 * 4 * 64 * 16 + 255) / 256, 256>>>(x);
    prep_wh<<<(9 * 4 * OCP * 16 + 255) / 256, 256>>>(w_off, w_mod);
    prep_xpad<<<(BB * CIN * PADW * PADW + 255) / 256, 256>>>(x);
    transpose_wconv<<<(OC_FIN * 576 + 255) / 256, 256>>>(w_conv);
    conv_mma_kernel<<<dim3(14, 16, 8), 512>>>(b_off, b_mod);
    deform_gemm_kernel<<<dim3(HH, BB), 256>>>(out);
}

// round 12
// speedup vs baseline: 2.3510x; 1.0100x over previous
#include <cuda_runtime.h>
#include <cuda_bf16.h>
#include <cuda_fp16.h>
#include <cstdint>

// Problem constants
#define BB   8
#define CIN  64
#define HH   64
#define WW   64
#define OCH_OFF 1152
#define OCH_TOT 1728
#define OCP     1792          // padded oc (14 * 128)
#define OC_FIN  128
#define MAXOFF  16.0f
#define PADW 100              // padded plane 100x100, border 17

// Scratch
__device__ float g_om[(size_t)BB * OCH_TOT * HH * WW];   // conv out [b][r][y][x]
__device__ float g_wt[576 * 128];                        // w_conv transposed [ck][oc]
// zero-padded x: [b][c][100][100], (yy,xx) = (y+17, x+17)
__device__ float g_xpad[(size_t)BB * CIN * PADW * PADW];
// shifted x, fp16: g_xth[kj][b][yy 0..65][cc 0..3][px 0..63][cic 0..15]
__device__ __half g_xth[3 * 8 * 66 * 4 * 64 * 16];
// conv weights fp16 split: g_wh[t][cc][ocp][cic] (zeros oc>=1728)
__device__ __half g_wh_hi[9 * 4 * OCP * 16];
__device__ __half g_wh_lo[9 * 4 * OCP * 16];

// ======================= helpers =======================
__device__ __forceinline__ uint32_t smem_u32(const void* p) {
    uint32_t a;
    asm("{ .reg .u64 t; cvta.to.shared.u64 t, %1; cvt.u32.u64 %0, t; }"
        : "=r"(a) : "l"(p));
    return a;
}
__device__ __forceinline__ void ldm_x4(uint32_t* r, uint32_t addr) {
    asm volatile("ldmatrix.sync.aligned.m8n8.x4.shared.b16 {%0,%1,%2,%3}, [%4];"
                 : "=r"(r[0]), "=r"(r[1]), "=r"(r[2]), "=r"(r[3]) : "r"(addr));
}
__device__ __forceinline__ void mma_f16(float* d, const uint32_t* a,
                                        uint32_t b0, uint32_t b1) {
    asm volatile(
        "mma.sync.aligned.m16n8k16.row.col.f32.f16.f16.f32 "
        "{%0,%1,%2,%3}, {%4,%5,%6,%7}, {%8,%9}, {%0,%1,%2,%3};"
        : "+f"(d[0]), "+f"(d[1]), "+f"(d[2]), "+f"(d[3])
        : "r"(a[0]), "r"(a[1]), "r"(a[2]), "r"(a[3]), "r"(b0), "r"(b1));
}

// ---------------- packed f32x2 helpers (deform kernel) ----------------
__device__ __forceinline__ unsigned long long ffma2(unsigned long long a,
                                                    unsigned long long b,
                                                    unsigned long long c) {
    unsigned long long d;
    asm("fma.rn.f32x2 %0, %1, %2, %3;" : "=l"(d) : "l"(a), "l"(b), "l"(c));
    return d;
}
__device__ __forceinline__ unsigned long long pack2(float lo, float hi) {
    unsigned long long d;
    asm("mov.b64 %0, {%1, %2};" : "=l"(d) : "f"(lo), "f"(hi));
    return d;
}
__device__ __forceinline__ void unpack2(unsigned long long v, float& lo, float& hi) {
    asm("mov.b64 {%0, %1}, %2;" : "=f"(lo), "=f"(hi) : "l"(v));
}

// ======================= Prep kernels =======================
__global__ void prep_xth(const float* __restrict__ x) {
    int i = blockIdx.x * 256 + threadIdx.x;
    const int TOT = 3 * 8 * 66 * 4 * 64 * 16;
    if (i >= TOT) return;
    int cic = i & 15;
    int t1 = i >> 4;
    int px = t1 & 63;
    int t2 = t1 >> 6;
    int cc = t2 & 3;
    int t3 = t2 >> 2;
    int yy = t3 % 66;
    int t4 = t3 / 66;
    int b  = t4 & 7;
    int kj = t4 >> 3;
    int c = cc * 16 + cic;
    int sy = yy - 1, sx = px + kj - 1;
    float v = 0.f;
    if (sy >= 0 && sy < HH && sx >= 0 && sx < WW)
        v = x[(((size_t)b * CIN + c) * HH + sy) * WW + sx];
    g_xth[i] = __float2half(v);
}

__global__ void prep_wh(const float* __restrict__ w_off, const float* __restrict__ w_mod) {
    int i = blockIdx.x * 256 + threadIdx.x;
    const int TOT = 9 * 4 * OCP * 16;
    if (i >= TOT) return;
    int cic = i & 15;
    int t1 = i >> 4;
    int oc = t1 % OCP;
    int tcc = t1 / OCP;
    int cc = tcc & 3;
    int tp = tcc >> 2;
    int c = cc * 16 + cic;
    float v = 0.f;
    if (oc < OCH_OFF)      v = w_off[((size_t)oc * CIN + c) * 9 + tp];
    else if (oc < OCH_TOT) v = w_mod[((size_t)(oc - OCH_OFF) * CIN + c) * 9 + tp];
    __half h = __float2half(v);
    g_wh_hi[i] = h;
    g_wh_lo[i] = __float2half(v - __half2float(h));
}

__global__ void prep_xpad(const float* __restrict__ x) {
    int i = blockIdx.x * 256 + threadIdx.x;
    const int TOT = BB * CIN * PADW * PADW;
    if (i >= TOT) return;
    int xx = i % PADW;
    int t1 = i / PADW;
    int yy = t1 % PADW;
    int bc = t1 / PADW;
    int sy = yy - 17, sx = xx - 17;
    float v = 0.f;
    if (sy >= 0 && sy < HH && sx >= 0 && sx < WW)
        v = x[((size_t)bc * HH + sy) * WW + sx];
    g_xpad[i] = v;
}

__global__ void transpose_wconv(const float* __restrict__ w_conv) {
    int i = blockIdx.x * 256 + threadIdx.x;
    if (i < OC_FIN * 576) {
        int oc = i / 576, ck = i % 576;
        g_wt[ck * 128 + oc] = w_conv[i];
    }
}

// ======================= Conv kernel: fp16 2-MMA split (exact R9) =========
// CTA: 128 oc x 128 px (2 image rows of one b). 8 warps: wm = w&3 (oc quad),
// wn = w>>2 (row). Warp tile 32 oc x 64 px. K = 9 taps x 4 chunks of 16.
// SMEM double buffer of {A_hi[128][48] ; A_lo[128][48] ; B[128][48]} = 36 KB.
#define SROW 48
#define ASZ 6144               // 128*48
#define BUFSZ 18432            // A_hi + A_lo + B
__global__ __launch_bounds__(256) void conv_mma_kernel(
    const float* __restrict__ b_off, const float* __restrict__ b_mod)
{
    __shared__ __align__(16) char smem[2 * BUFSZ];   // 36 KB
    const uint32_t sb = smem_u32(smem);
    const int tid = threadIdx.x;
    const int lane = tid & 31;
    const int w = tid >> 5;
    const int wm = w & 3;
    const int wn = w >> 2;
    const int ocBase = blockIdx.x * 128;
    const int y0 = blockIdx.y * 2;
    const int b  = blockIdx.z;

    float d[2][8][4];
#pragma unroll
    for (int mt = 0; mt < 2; mt++)
#pragma unroll
        for (int nt = 0; nt < 8; nt++)
#pragma unroll
            for (int e = 0; e < 4; e++) d[mt][nt][e] = 0.f;

    auto stage = [&](int s, int buf) {
        const int t = s >> 2, cc = s & 3;
        const int ki = t / 3, kj = t - ki * 3;
        char* base = smem + buf * BUFSZ;
#pragma unroll
        for (int ii = 0; ii < 3; ii++) {
            int i = tid + ii * 256;
            if (i < 512) {
                int hh = i >> 8, oc = (i >> 1) & 127, j = i & 1;
                const __half* src = (hh ? g_wh_lo : g_wh_hi)
                    + (((size_t)(t * 4 + cc) * OCP + ocBase + oc) << 4) + j * 8;
                *(uint4*)(base + hh * ASZ + oc * SROW + j * 16) = *(const uint4*)src;
            } else {
                i -= 512;
                int px = (i >> 1) & 127, j = i & 1;
                int yy = y0 + (px >> 6) + ki;
                const __half* src = g_xth
                    + ((size_t)(((kj * 8 + b) * 66 + yy) * 4 + cc) << 10)
                    + ((px & 63) << 4) + j * 8;
                *(uint4*)(base + 2 * ASZ + px * SROW + j * 16) = *(const uint4*)src;
            }
        }
    };

    stage(0, 0);
    __syncthreads();

    const int arowL = (lane & 7) + ((lane >> 3) & 1) * 8;
    const int acolB = ((lane >> 4) & 1) * 16;

    for (int s = 0; s < 36; s++) {
        const int buf = s & 1;
        if (s + 1 < 36) stage(s + 1, 1 - buf);

        const uint32_t sA = sb + buf * BUFSZ;
        const uint32_t sB = sA + 2 * ASZ;

        uint32_t a[2][2][4];
#pragma unroll
        for (int mt = 0; mt < 2; mt++)
#pragma unroll
            for (int hh = 0; hh < 2; hh++)
                ldm_x4(a[mt][hh],
                       sA + hh * ASZ + (wm * 32 + mt * 16 + arowL) * SROW + acolB);

#pragma unroll
        for (int p = 0; p < 4; p++) {
            uint32_t bh[4];
            ldm_x4(bh, sB + (wn * 64 + p * 16 + arowL) * SROW + acolB);
#pragma unroll
            for (int mt = 0; mt < 2; mt++) {
#pragma unroll
                for (int q = 0; q < 2; q++) {
                    float* dd = d[mt][p * 2 + q];
                    mma_f16(dd, a[mt][0], bh[q], bh[q + 2]);   // Wh * X
                    mma_f16(dd, a[mt][1], bh[q], bh[q + 2]);   // Wl * X
                }
            }
        }
        __syncthreads();
    }

    const int ocW = ocBase + wm * 32;
    if (ocW >= OCH_TOT) return;
    const int y = y0 + wn;
#pragma unroll
    for (int mt = 0; mt < 2; mt++) {
        int r0 = ocW + mt * 16 + (lane >> 2);
        int r1 = r0 + 8;
        float bias0 = (r0 < OCH_OFF) ? __ldg(&b_off[r0]) : __ldg(&b_mod[r0 - OCH_OFF]);
        float bias1 = (r1 < OCH_OFF) ? __ldg(&b_off[r1]) : __ldg(&b_mod[r1 - OCH_OFF]);
        bool c0 = r0 < OCH_OFF, c1 = r1 < OCH_OFF;
        float* base0 = &g_om[(((size_t)b * OCH_TOT + r0) * HH + y) * WW];
        float* base1 = &g_om[(((size_t)b * OCH_TOT + r1) * HH + y) * WW];
#pragma unroll
        for (int nt = 0; nt < 8; nt++) {
            int col = nt * 8 + (lane & 3) * 2;
            float2 v0, v1;
            v0.x = d[mt][nt][0] + bias0; v0.y = d[mt][nt][1] + bias0;
            v1.x = d[mt][nt][2] + bias1; v1.y = d[mt][nt][3] + bias1;
            if (c0) {
                v0.x = fminf(fmaxf(v0.x, -MAXOFF), MAXOFF);
                v0.y = fminf(fmaxf(v0.y, -MAXOFF), MAXOFF);
            }
            if (c1) {
                v1.x = fminf(fmaxf(v1.x, -MAXOFF), MAXOFF);
                v1.y = fminf(fmaxf(v1.y, -MAXOFF), MAXOFF);
            }
            *(float2*)(base0 + col) = v0;
            *(float2*)(base1 + col) = v1;
        }
    }
}

// ======================= Deform + final GEMM (pipelined FFMA2) ============
// CTA = one (b, y) row: 64 px x 128 oc. 256 threads; chunks of 4 channels.
// Software pipeline: sample chunk i+1 while GEMMing chunk i.
// Dynamic smem 55296 B: ss[2][2304] @0, wcs[2][4608] @18432.
__global__ __launch_bounds__(256) void deform_gemm_kernel(float* __restrict__ out)
{
    extern __shared__ __align__(16) float dsm[];
    float* ssb = dsm;              // 2 x 2304
    float* wcb = dsm + 4608;       // 2 x 4608

    const int y = blockIdx.x;
    const int b = blockIdx.y;
    const int tid = threadIdx.x;
    const int tx = tid & 15;
    const int ty = tid >> 4;
    const int px0 = tx * 4;
    const int oc0 = ty * 8;

    unsigned long long acc2[4][4];
#pragma unroll
    for (int p = 0; p < 4; p++)
#pragma unroll
        for (int j = 0; j < 4; j++) acc2[p][j] = 0ull;

    const float* xpb = g_xpad + (size_t)b * CIN * (PADW * PADW);
    const float* omb = g_om + (size_t)b * OCH_TOT * (HH * WW);

    auto sample_chunk = [&](int c0, float* ss, float* wcs) {
        for (int idx = tid; idx < 36 * 128; idx += 256)
            wcs[idx] = g_wt[(c0 * 9 + (idx >> 7)) * 128 + (idx & 127)];
        for (int s = tid; s < 4 * 9 * 64; s += 256) {
            int px = s & 63;
            int k  = (s >> 6) % 9;
            int cc = s / 576;
            int c  = c0 + cc;
            int ki = k / 3, kj = k % 3;
            float dy = __ldg(omb + (size_t)(c * 18 + 2 * k) * 4096 + y * WW + px);
            float dx = __ldg(omb + (size_t)(c * 18 + 2 * k + 1) * 4096 + y * WW + px);
            float m  = __ldg(omb + (size_t)(OCH_OFF + c * 9 + k) * 4096 + y * WW + px);
            // padded-plane coords (always in [0, 97])
            float py  = dy + (float)(y + ki + 16);
            float pxf = dx + (float)(px + kj + 16);
            int iy = (int)py, ix = (int)pxf;
            float wy = py - (float)iy, wx = pxf - (float)ix;
            const float* p = xpb + (size_t)c * (PADW * PADW) + iy * PADW + ix;
            float v00 = __ldg(p), v01 = __ldg(p + 1);
            float v10 = __ldg(p + PADW), v11 = __ldg(p + PADW + 1);
            float t0 = v00 + wx * (v01 - v00);
            float t1 = v10 + wx * (v11 - v10);
            ss[s] = (t0 + wy * (t1 - t0)) * m;
        }
    };

    sample_chunk(0, ssb, wcb);
    __syncthreads();

    for (int ci = 0; ci < 16; ci++) {
        float* ss  = ssb + (ci & 1) * 2304;
        float* wcs = wcb + (ci & 1) * 4608;
        if (ci + 1 < 16)
            sample_chunk((ci + 1) * 4, ssb + ((ci + 1) & 1) * 2304,
                         wcb + ((ci + 1) & 1) * 4608);

#pragma unroll
        for (int ck = 0; ck < 36; ck++) {
            float4 sv4 = *(const float4*)&ss[ck * 64 + px0];
            unsigned long long sp[4];
            sp[0] = pack2(sv4.x, sv4.x);
            sp[1] = pack2(sv4.y, sv4.y);
            sp[2] = pack2(sv4.z, sv4.z);
            sp[3] = pack2(sv4.w, sv4.w);
            ulonglong2 w0 = *(const ulonglong2*)&wcs[ck * 128 + oc0];
            ulonglong2 w1 = *(const ulonglong2*)&wcs[ck * 128 + oc0 + 4];
#pragma unroll
            for (int j = 0; j < 4; j++) {
                acc2[0][j] = ffma2(w0.x, sp[j], acc2[0][j]);
                acc2[1][j] = ffma2(w0.y, sp[j], acc2[1][j]);
                acc2[2][j] = ffma2(w1.x, sp[j], acc2[2][j]);
                acc2[3][j] = ffma2(w1.y, sp[j], acc2[3][j]);
            }
        }
        __syncthreads();
    }

#pragma unroll
    for (int p = 0; p < 4; p++) {
        float lo[4], hi[4];
#pragma unroll
        for (int j = 0; j < 4; j++) unpack2(acc2[p][j], lo[j], hi[j]);
        float4 vlo = make_float4(lo[0], lo[1], lo[2], lo[3]);
        float4 vhi = make_float4(hi[0], hi[1], hi[2], hi[3]);
        int oc = oc0 + 2 * p;
        *(float4*)&out[(((size_t)b * OC_FIN + oc) * HH + y) * WW + px0] = vlo;
        *(float4*)&out[(((size_t)b * OC_FIN + oc + 1) * HH + y) * WW + px0] = vhi;
    }
}

// ---------------------------------------------------------------------------
extern "C" void kernel_launch(void* const* d_in, const int* in_sizes, int n_in,
                              void* d_out, int out_size)
{
    const float* x      = (const float*)d_in[0];
    const float* w_off  = (const float*)d_in[1];
    const float* b_off  = (const float*)d_in[2];
    const float* w_mod  = (const float*)d_in[3];
    const float* b_mod  = (const float*)d_in[4];
    const float* w_conv = (const float*)d_in[5];
    float* out = (float*)d_out;

    cudaFuncSetAttribute(deform_gemm_kernel,
                         cudaFuncAttributeMaxDynamicSharedMemorySize, 55296);

    prep_xth<<<(3 * 8 * 66 * 4 * 64 * 16 + 255) / 256, 256>>>(x);
    prep_wh<<<(9 * 4 * OCP * 16 + 255) / 256, 256>>>(w_off, w_mod);
    prep_xpad<<<(BB * CIN * PADW * PADW + 255) / 256, 256>>>(x);
    transpose_wconv<<<(OC_FIN * 576 + 255) / 256, 256>>>(w_conv);
    conv_mma_kernel<<<dim3(14, 32, 8), 256>>>(b_off, b_mod);
    deform_gemm_kernel<<<dim3(HH, BB), 256, 55296>>>(out);
}

// round 13
// speedup vs baseline: 2.7175x; 1.1559x over previous
#include <cuda_runtime.h>
#include <cuda_bf16.h>
#include <cuda_fp16.h>
#include <cstdint>

// Problem constants
#define BB   8
#define CIN  64
#define HH   64
#define WW   64
#define OCH_OFF 1152
#define OCH_TOT 1728
#define OCP     1792          // padded oc (14 * 128)
#define OC_FIN  128
#define MAXOFF  16.0f
#define PADW 100              // padded plane 100x100, border 17

// Scratch
__device__ float g_om[(size_t)BB * OCH_TOT * HH * WW];   // conv out [b][r][y][x]
__device__ float g_wt[576 * 128];                        // w_conv transposed [ck][oc]
// zero-padded x: [b][c][100][100], (yy,xx) = (y+17, x+17)
__device__ float g_xpad[(size_t)BB * CIN * PADW * PADW];
// shifted x, fp16: g_xth[kj][b][yy 0..65][cc 0..3][px 0..63][cic 0..15]
__device__ __half g_xth[3 * 8 * 66 * 4 * 64 * 16];
// conv weights fp16 split: g_wh[t][cc][ocp][cic] (zeros oc>=1728)
__device__ __half g_wh_hi[9 * 4 * OCP * 16];
__device__ __half g_wh_lo[9 * 4 * OCP * 16];

// ======================= helpers =======================
__device__ __forceinline__ uint32_t smem_u32(const void* p) {
    uint32_t a;
    asm("{ .reg .u64 t; cvta.to.shared.u64 t, %1; cvt.u32.u64 %0, t; }"
        : "=r"(a) : "l"(p));
    return a;
}
__device__ __forceinline__ void ldm_x4(uint32_t* r, uint32_t addr) {
    asm volatile("ldmatrix.sync.aligned.m8n8.x4.shared.b16 {%0,%1,%2,%3}, [%4];"
                 : "=r"(r[0]), "=r"(r[1]), "=r"(r[2]), "=r"(r[3]) : "r"(addr));
}
__device__ __forceinline__ void mma_f16(float* d, const uint32_t* a,
                                        uint32_t b0, uint32_t b1) {
    asm volatile(
        "mma.sync.aligned.m16n8k16.row.col.f32.f16.f16.f32 "
        "{%0,%1,%2,%3}, {%4,%5,%6,%7}, {%8,%9}, {%0,%1,%2,%3};"
        : "+f"(d[0]), "+f"(d[1]), "+f"(d[2]), "+f"(d[3])
        : "r"(a[0]), "r"(a[1]), "r"(a[2]), "r"(a[3]), "r"(b0), "r"(b1));
}

// ---------------- packed f32x2 helpers (deform kernel) ----------------
__device__ __forceinline__ unsigned long long ffma2(unsigned long long a,
                                                    unsigned long long b,
                                                    unsigned long long c) {
    unsigned long long d;
    asm("fma.rn.f32x2 %0, %1, %2, %3;" : "=l"(d) : "l"(a), "l"(b), "l"(c));
    return d;
}
__device__ __forceinline__ unsigned long long pack2(float lo, float hi) {
    unsigned long long d;
    asm("mov.b64 %0, {%1, %2};" : "=l"(d) : "f"(lo), "f"(hi));
    return d;
}
__device__ __forceinline__ void unpack2(unsigned long long v, float& lo, float& hi) {
    asm("mov.b64 {%0, %1}, %2;" : "=f"(lo), "=f"(hi) : "l"(v));
}

// ======================= Prep kernels =======================
__global__ void prep_xth(const float* __restrict__ x) {
    int i = blockIdx.x * 256 + threadIdx.x;
    const int TOT = 3 * 8 * 66 * 4 * 64 * 16;
    if (i >= TOT) return;
    int cic = i & 15;
    int t1 = i >> 4;
    int px = t1 & 63;
    int t2 = t1 >> 6;
    int cc = t2 & 3;
    int t3 = t2 >> 2;
    int yy = t3 % 66;
    int t4 = t3 / 66;
    int b  = t4 & 7;
    int kj = t4 >> 3;
    int c = cc * 16 + cic;
    int sy = yy - 1, sx = px + kj - 1;
    float v = 0.f;
    if (sy >= 0 && sy < HH && sx >= 0 && sx < WW)
        v = x[(((size_t)b * CIN + c) * HH + sy) * WW + sx];
    g_xth[i] = __float2half(v);
}

__global__ void prep_wh(const float* __restrict__ w_off, const float* __restrict__ w_mod) {
    int i = blockIdx.x * 256 + threadIdx.x;
    const int TOT = 9 * 4 * OCP * 16;
    if (i >= TOT) return;
    int cic = i & 15;
    int t1 = i >> 4;
    int oc = t1 % OCP;
    int tcc = t1 / OCP;
    int cc = tcc & 3;
    int tp = tcc >> 2;
    int c = cc * 16 + cic;
    float v = 0.f;
    if (oc < OCH_OFF)      v = w_off[((size_t)oc * CIN + c) * 9 + tp];
    else if (oc < OCH_TOT) v = w_mod[((size_t)(oc - OCH_OFF) * CIN + c) * 9 + tp];
    __half h = __float2half(v);
    g_wh_hi[i] = h;
    g_wh_lo[i] = __float2half(v - __half2float(h));
}

__global__ void prep_xpad(const float* __restrict__ x) {
    int i = blockIdx.x * 256 + threadIdx.x;
    const int TOT = BB * CIN * PADW * PADW;
    if (i >= TOT) return;
    int xx = i % PADW;
    int t1 = i / PADW;
    int yy = t1 % PADW;
    int bc = t1 / PADW;
    int sy = yy - 17, sx = xx - 17;
    float v = 0.f;
    if (sy >= 0 && sy < HH && sx >= 0 && sx < WW)
        v = x[((size_t)bc * HH + sy) * WW + sx];
    g_xpad[i] = v;
}

__global__ void transpose_wconv(const float* __restrict__ w_conv) {
    int i = blockIdx.x * 256 + threadIdx.x;
    if (i < OC_FIN * 576) {
        int oc = i / 576, ck = i % 576;
        g_wt[ck * 128 + oc] = w_conv[i];
    }
}

// ======================= Conv kernel: fp16 split, mask CTAs 1-MMA =========
// CTA: 128 oc x 128 px (2 image rows of one b). 8 warps: wm = w&3 (oc quad),
// wn = w>>2 (row). Warp tile 32 oc x 64 px. K = 9 taps x 4 chunks of 16.
// Offset CTAs (ocBase < 1152): 2-MMA split (Wh + Wl).
// Mask CTAs (ocBase >= 1152): single Wh MMA (mask tolerates fp16 w rounding).
// SMEM double buffer of {A_hi[128][48] ; A_lo[128][48] ; B[128][48]} = 36 KB.
#define SROW 48
#define ASZ 6144               // 128*48
#define BUFSZ 18432            // A_hi + A_lo + B
__global__ __launch_bounds__(256) void conv_mma_kernel(
    const float* __restrict__ b_off, const float* __restrict__ b_mod)
{
    __shared__ __align__(16) char smem[2 * BUFSZ];   // 36 KB
    const uint32_t sb = smem_u32(smem);
    const int tid = threadIdx.x;
    const int lane = tid & 31;
    const int w = tid >> 5;
    const int wm = w & 3;
    const int wn = w >> 2;
    const int ocBase = blockIdx.x * 128;
    const int y0 = blockIdx.y * 2;
    const int b  = blockIdx.z;
    const bool needLo = (ocBase < OCH_OFF);   // block-uniform

    float d[2][8][4];
#pragma unroll
    for (int mt = 0; mt < 2; mt++)
#pragma unroll
        for (int nt = 0; nt < 8; nt++)
#pragma unroll
            for (int e = 0; e < 4; e++) d[mt][nt][e] = 0.f;

    auto stage = [&](int s, int buf) {
        const int t = s >> 2, cc = s & 3;
        const int ki = t / 3, kj = t - ki * 3;
        char* base = smem + buf * BUFSZ;
#pragma unroll
        for (int ii = 0; ii < 3; ii++) {
            int i = tid + ii * 256;
            if (i < 512) {
                int hh = i >> 8, oc = (i >> 1) & 127, j = i & 1;
                if (hh == 0 || needLo) {
                    const __half* src = (hh ? g_wh_lo : g_wh_hi)
                        + (((size_t)(t * 4 + cc) * OCP + ocBase + oc) << 4) + j * 8;
                    *(uint4*)(base + hh * ASZ + oc * SROW + j * 16) = *(const uint4*)src;
                }
            } else {
                i -= 512;
                int px = (i >> 1) & 127, j = i & 1;
                int yy = y0 + (px >> 6) + ki;
                const __half* src = g_xth
                    + ((size_t)(((kj * 8 + b) * 66 + yy) * 4 + cc) << 10)
                    + ((px & 63) << 4) + j * 8;
                *(uint4*)(base + 2 * ASZ + px * SROW + j * 16) = *(const uint4*)src;
            }
        }
    };

    stage(0, 0);
    __syncthreads();

    const int arowL = (lane & 7) + ((lane >> 3) & 1) * 8;
    const int acolB = ((lane >> 4) & 1) * 16;

    for (int s = 0; s < 36; s++) {
        const int buf = s & 1;
        if (s + 1 < 36) stage(s + 1, 1 - buf);

        const uint32_t sA = sb + buf * BUFSZ;
        const uint32_t sB = sA + 2 * ASZ;

        uint32_t a[2][2][4];
#pragma unroll
        for (int mt = 0; mt < 2; mt++) {
            ldm_x4(a[mt][0], sA + (wm * 32 + mt * 16 + arowL) * SROW + acolB);
            if (needLo)
                ldm_x4(a[mt][1], sA + ASZ + (wm * 32 + mt * 16 + arowL) * SROW + acolB);
        }

#pragma unroll
        for (int p = 0; p < 4; p++) {
            uint32_t bh[4];
            ldm_x4(bh, sB + (wn * 64 + p * 16 + arowL) * SROW + acolB);
#pragma unroll
            for (int mt = 0; mt < 2; mt++) {
#pragma unroll
                for (int q = 0; q < 2; q++) {
                    float* dd = d[mt][p * 2 + q];
                    mma_f16(dd, a[mt][0], bh[q], bh[q + 2]);       // Wh * X
                    if (needLo)
                        mma_f16(dd, a[mt][1], bh[q], bh[q + 2]);   // Wl * X
                }
            }
        }
        __syncthreads();
    }

    const int ocW = ocBase + wm * 32;
    if (ocW >= OCH_TOT) return;
    const int y = y0 + wn;
#pragma unroll
    for (int mt = 0; mt < 2; mt++) {
        int r0 = ocW + mt * 16 + (lane >> 2);
        int r1 = r0 + 8;
        float bias0 = (r0 < OCH_OFF) ? __ldg(&b_off[r0]) : __ldg(&b_mod[r0 - OCH_OFF]);
        float bias1 = (r1 < OCH_OFF) ? __ldg(&b_off[r1]) : __ldg(&b_mod[r1 - OCH_OFF]);
        bool c0 = r0 < OCH_OFF, c1 = r1 < OCH_OFF;
        float* base0 = &g_om[(((size_t)b * OCH_TOT + r0) * HH + y) * WW];
        float* base1 = &g_om[(((size_t)b * OCH_TOT + r1) * HH + y) * WW];
#pragma unroll
        for (int nt = 0; nt < 8; nt++) {
            int col = nt * 8 + (lane & 3) * 2;
            float2 v0, v1;
            v0.x = d[mt][nt][0] + bias0; v0.y = d[mt][nt][1] + bias0;
            v1.x = d[mt][nt][2] + bias1; v1.y = d[mt][nt][3] + bias1;
            if (c0) {
                v0.x = fminf(fmaxf(v0.x, -MAXOFF), MAXOFF);
                v0.y = fminf(fmaxf(v0.y, -MAXOFF), MAXOFF);
            }
            if (c1) {
                v1.x = fminf(fmaxf(v1.x, -MAXOFF), MAXOFF);
                v1.y = fminf(fmaxf(v1.y, -MAXOFF), MAXOFF);
            }
            *(float2*)(base0 + col) = v0;
            *(float2*)(base1 + col) = v1;
        }
    }
}

// ======================= Deform + final GEMM (FFMA2, padded sampling) =====
// CTA = one (b, y) row: 64 px x 128 oc. 256 threads; channel chunks of 4.
__global__ __launch_bounds__(256) void deform_gemm_kernel(float* __restrict__ out)
{
    const int y = blockIdx.x;
    const int b = blockIdx.y;
    const int tid = threadIdx.x;
    const int tx = tid & 15;
    const int ty = tid >> 4;
    const int px0 = tx * 4;
    const int oc0 = ty * 8;

    __shared__ __align__(16) float ss[4 * 9 * 64];
    __shared__ __align__(16) float wcs[36][128];

    unsigned long long acc2[4][4];
#pragma unroll
    for (int p = 0; p < 4; p++)
#pragma unroll
        for (int j = 0; j < 4; j++) acc2[p][j] = 0ull;

    const float* xpb = g_xpad + (size_t)b * CIN * (PADW * PADW);
    const float* omb = g_om + (size_t)b * OCH_TOT * (HH * WW);

    for (int c0 = 0; c0 < CIN; c0 += 4) {
        for (int idx = tid; idx < 36 * 128; idx += 256) {
            ((float*)wcs)[idx] = g_wt[(c0 * 9 + (idx >> 7)) * 128 + (idx & 127)];
        }
        for (int s = tid; s < 4 * 9 * 64; s += 256) {
            int px = s & 63;
            int k  = (s >> 6) % 9;
            int cc = s / 576;
            int c  = c0 + cc;
            int ki = k / 3, kj = k % 3;
            float dy = __ldg(omb + (size_t)(c * 18 + 2 * k) * 4096 + y * WW + px);
            float dx = __ldg(omb + (size_t)(c * 18 + 2 * k + 1) * 4096 + y * WW + px);
            float m  = __ldg(omb + (size_t)(OCH_OFF + c * 9 + k) * 4096 + y * WW + px);
            // padded-plane coords (always in [0, 97])
            float py  = dy + (float)(y + ki + 16);
            float pxf = dx + (float)(px + kj + 16);
            int iy = (int)py, ix = (int)pxf;
            float wy = py - (float)iy, wx = pxf - (float)ix;
            const float* p = xpb + (size_t)c * (PADW * PADW) + iy * PADW + ix;
            float v00 = __ldg(p), v01 = __ldg(p + 1);
            float v10 = __ldg(p + PADW), v11 = __ldg(p + PADW + 1);
            float t0 = v00 + wx * (v01 - v00);
            float t1 = v10 + wx * (v11 - v10);
            ss[s] = (t0 + wy * (t1 - t0)) * m;
        }
        __syncthreads();

#pragma unroll
        for (int ck = 0; ck < 36; ck++) {
            float4 sv4 = *(const float4*)&ss[ck * 64 + px0];
            unsigned long long sp[4];
            sp[0] = pack2(sv4.x, sv4.x);
            sp[1] = pack2(sv4.y, sv4.y);
            sp[2] = pack2(sv4.z, sv4.z);
            sp[3] = pack2(sv4.w, sv4.w);
            ulonglong2 w0 = *(const ulonglong2*)&wcs[ck][oc0];
            ulonglong2 w1 = *(const ulonglong2*)&wcs[ck][oc0 + 4];
#pragma unroll
            for (int j = 0; j < 4; j++) {
                acc2[0][j] = ffma2(w0.x, sp[j], acc2[0][j]);
                acc2[1][j] = ffma2(w0.y, sp[j], acc2[1][j]);
                acc2[2][j] = ffma2(w1.x, sp[j], acc2[2][j]);
                acc2[3][j] = ffma2(w1.y, sp[j], acc2[3][j]);
            }
        }
        __syncthreads();
    }

#pragma unroll
    for (int p = 0; p < 4; p++) {
        float lo[4], hi[4];
#pragma unroll
        for (int j = 0; j < 4; j++) unpack2(acc2[p][j], lo[j], hi[j]);
        float4 vlo = make_float4(lo[0], lo[1], lo[2], lo[3]);
        float4 vhi = make_float4(hi[0], hi[1], hi[2], hi[3]);
        int oc = oc0 + 2 * p;
        *(float4*)&out[(((size_t)b * OC_FIN + oc) * HH + y) * WW + px0] = vlo;
        *(float4*)&out[(((size_t)b * OC_FIN + oc + 1) * HH + y) * WW + px0] = vhi;
    }
}

// ---------------------------------------------------------------------------
extern "C" void kernel_launch(void* const* d_in, const int* in_sizes, int n_in,
                              void* d_out, int out_size)
{
    const float* x      = (const float*)d_in[0];
    const float* w_off  = (const float*)d_in[1];
    const float* b_off  = (const float*)d_in[2];
    const float* w_mod  = (const float*)d_in[3];
    const float* b_mod  = (const float*)d_in[4];
    const float* w_conv = (const float*)d_in[5];
    float* out = (float*)d_out;

    prep_xth<<<(3 * 8 * 66 * 4 * 64 * 16 + 255) / 256, 256>>>(x);
    prep_wh<<<(9 * 4 * OCP * 16 + 255) / 256, 256>>>(w_off, w_mod);
    prep_xpad<<<(BB * CIN * PADW * PADW + 255) / 256, 256>>>(x);
    transpose_wconv<<<(OC_FIN * 576 + 255) / 256, 256>>>(w_conv);
    conv_mma_kernel<<<dim3(14, 32, 8), 256>>>(b_off, b_mod);
    deform_gemm_kernel<<<dim3(HH, BB), 256>>>(out);
}